// round 1
// baseline (speedup 1.0000x reference)
#include <cuda_runtime.h>

#define D 128
#define NN 50000
#define NE 500000

// Scratch (allocation-free rule: __device__ globals)
__device__ float g_psrc[(size_t)NN * D];   // src @ W_s2e^T
__device__ float g_ptgt[(size_t)NN * D];   // tgt @ W_t2e^T
__device__ float g_agg [(size_t)NN * D];   // segment_sum(edge_out, tgt_idx)
__device__ float g_wt  [5 * D * D];        // transposed weights: [k][j] layout

// ---------------------------------------------------------------------------
// K-1: zero the aggregation buffer (graph-capturable, no memset/symbol calls)
// ---------------------------------------------------------------------------
__global__ void k_zero() {
    size_t i = ((size_t)blockIdx.x * blockDim.x + threadIdx.x) * 4;
    if (i < (size_t)NN * D) {
        *(float4*)(g_agg + i) = make_float4(0.f, 0.f, 0.f, 0.f);
    }
}

// ---------------------------------------------------------------------------
// K0: transpose the 5 weight matrices so GEMM smem loads are coalesced,
//     conflict-free rows Wt[k][j] = W[j][k]. 80KB total -> negligible.
// ---------------------------------------------------------------------------
__global__ void k_transpose(const float* __restrict__ s2e, const float* __restrict__ t2e,
                            const float* __restrict__ e2e, const float* __restrict__ e2t,
                            const float* __restrict__ t2t) {
    const float* W[5] = {s2e, t2e, e2e, e2t, t2t};
    const float* src = W[blockIdx.x];
    float* dst = g_wt + blockIdx.x * D * D;
    for (int t = threadIdx.x; t < D * D; t += blockDim.x) {
        int k = t >> 7, j = t & 127;
        dst[t] = src[j * D + k];
    }
}

// ---------------------------------------------------------------------------
// Shared GEMM machinery: 128x128 tile, 256 threads, TM=TN=8.
// out[i][j] = sum_k Xs[i][k] * Ws[k][j]   (Ws already K-major / transposed)
// ---------------------------------------------------------------------------
__device__ __forceinline__ void load_tile(float* dst, const float* __restrict__ src,
                                          int row0, int nrows) {
    int t = threadIdx.x;
    #pragma unroll
    for (int it = 0; it < 16; it++) {
        int i = t + it * 256;          // float4 index, 4096 total
        int r = i >> 5;
        int c = (i & 31) << 2;
        float4 v = make_float4(0.f, 0.f, 0.f, 0.f);
        if (row0 + r < nrows) v = *(const float4*)(src + (size_t)(row0 + r) * D + c);
        *(float4*)(dst + r * D + c) = v;
    }
}

__device__ __forceinline__ void gemm128(const float* __restrict__ Xs,
                                        const float* __restrict__ Ws,
                                        float (&acc)[8][8], int tr, int tc) {
    const float* xb = Xs + tr * 8 * D;
    const float* wb = Ws + tc * 8;
    #pragma unroll 4
    for (int k = 0; k < D; k++) {
        float4 w0 = *(const float4*)(wb + k * D);
        float4 w1 = *(const float4*)(wb + k * D + 4);
        float x[8];
        #pragma unroll
        for (int i = 0; i < 8; i++) x[i] = xb[i * D + k];
        #pragma unroll
        for (int i = 0; i < 8; i++) {
            acc[i][0] = fmaf(x[i], w0.x, acc[i][0]);
            acc[i][1] = fmaf(x[i], w0.y, acc[i][1]);
            acc[i][2] = fmaf(x[i], w0.z, acc[i][2]);
            acc[i][3] = fmaf(x[i], w0.w, acc[i][3]);
            acc[i][4] = fmaf(x[i], w1.x, acc[i][4]);
            acc[i][5] = fmaf(x[i], w1.y, acc[i][5]);
            acc[i][6] = fmaf(x[i], w1.z, acc[i][6]);
            acc[i][7] = fmaf(x[i], w1.w, acc[i][7]);
        }
    }
}

__device__ __forceinline__ float silu(float m) {
    return m * (1.f / (1.f + __expf(-m)));
}

// ---------------------------------------------------------------------------
// K1: node projections psrc/ptgt (blockIdx.y selects which)
// ---------------------------------------------------------------------------
__global__ void __launch_bounds__(256, 1) k_nodeproj(const float* __restrict__ src,
                                                     const float* __restrict__ tgt) {
    extern __shared__ float smem[];
    float* Xs = smem;
    float* Ws = smem + D * D;
    int r0 = blockIdx.x * 128;
    const float* X;
    const float* Wt;
    float* O;
    if (blockIdx.y == 0) { X = src; Wt = g_wt;          O = g_psrc; }
    else                 { X = tgt; Wt = g_wt + D * D;  O = g_ptgt; }
    load_tile(Xs, X, r0, NN);
    load_tile(Ws, Wt, 0, D);
    __syncthreads();
    int tc = threadIdx.x & 15, tr = threadIdx.x >> 4;
    float acc[8][8] = {};
    gemm128(Xs, Ws, acc, tr, tc);
    int c0 = tc * 8;
    #pragma unroll
    for (int i = 0; i < 8; i++) {
        int n = r0 + tr * 8 + i;
        if (n < NN) {
            *(float4*)(O + (size_t)n * D + c0)     = make_float4(acc[i][0], acc[i][1], acc[i][2], acc[i][3]);
            *(float4*)(O + (size_t)n * D + c0 + 4) = make_float4(acc[i][4], acc[i][5], acc[i][6], acc[i][7]);
        }
    }
}

// ---------------------------------------------------------------------------
// K2: fused edge update.  msg = edge@We2e^T + gather(psrc) + gather(ptgt)
//     edge_out = edge + LN(silu(msg)); atomically accumulate into g_agg[tgt].
//     LN is done entirely in registers via half-warp (16-lane) reductions:
//     one row of 128 outputs lives on 16 threads (8 each).
// ---------------------------------------------------------------------------
__global__ void __launch_bounds__(256, 1) k_edge(
    const float* __restrict__ edge, const int* __restrict__ src_idx,
    const int* __restrict__ tgt_idx, const float* __restrict__ g1,
    const float* __restrict__ b1, float* __restrict__ edge_out) {
    extern __shared__ float smem[];
    float* Xs = smem;
    float* Ws = smem + D * D;
    int e0 = blockIdx.x * 128;
    load_tile(Xs, edge, e0, NE);
    load_tile(Ws, g_wt + 2 * D * D, 0, D);
    __syncthreads();
    int tc = threadIdx.x & 15, tr = threadIdx.x >> 4;
    float acc[8][8] = {};
    gemm128(Xs, Ws, acc, tr, tc);

    int c0 = tc * 8;
    float gg[8], bb[8];
    #pragma unroll
    for (int j = 0; j < 8; j++) { gg[j] = g1[c0 + j]; bb[j] = b1[c0 + j]; }

    #pragma unroll
    for (int i = 0; i < 8; i++) {
        int r = tr * 8 + i;
        int e = e0 + r;
        bool valid = e < NE;
        int si = valid ? src_idx[e] : 0;
        int ti = valid ? tgt_idx[e] : 0;
        const float* ps = g_psrc + (size_t)si * D + c0;
        const float* pt = g_ptgt + (size_t)ti * D + c0;
        float4 p0 = *(const float4*)ps;
        float4 p1 = *(const float4*)(ps + 4);
        float4 q0 = *(const float4*)pt;
        float4 q1 = *(const float4*)(pt + 4);
        float add[8] = {p0.x + q0.x, p0.y + q0.y, p0.z + q0.z, p0.w + q0.w,
                        p1.x + q1.x, p1.y + q1.y, p1.z + q1.z, p1.w + q1.w};
        float s[8];
        float sum = 0.f, sq = 0.f;
        #pragma unroll
        for (int j = 0; j < 8; j++) {
            float sv = silu(acc[i][j] + add[j]);
            s[j] = sv; sum += sv; sq += sv * sv;
        }
        // half-warp reduction: a row's 16 threads are lanes [0..15] or [16..31]
        #pragma unroll
        for (int o = 1; o < 16; o <<= 1) {
            sum += __shfl_xor_sync(0xffffffffu, sum, o);
            sq  += __shfl_xor_sync(0xffffffffu, sq,  o);
        }
        float mean = sum * (1.f / D);
        float var  = sq  * (1.f / D) - mean * mean;
        float rstd = rsqrtf(var + 1e-5f);
        if (valid) {
            float o8[8];
            #pragma unroll
            for (int j = 0; j < 8; j++)
                o8[j] = (s[j] - mean) * rstd * gg[j] + bb[j] + Xs[r * D + c0 + j];
            *(float4*)(edge_out + (size_t)e * D + c0)     = make_float4(o8[0], o8[1], o8[2], o8[3]);
            *(float4*)(edge_out + (size_t)e * D + c0 + 4) = make_float4(o8[4], o8[5], o8[6], o8[7]);
            float* ap = g_agg + (size_t)ti * D + c0;
            #pragma unroll
            for (int j = 0; j < 8; j++) atomicAdd(ap + j, o8[j]);
        }
    }
}

// ---------------------------------------------------------------------------
// K3: target update.  tgt_msg = agg@We2t^T + tgt@Wt2t^T (two accumulated
//     GEMM passes); tgt_out = tgt + LN(silu(tgt_msg)). Residual comes from Xs
//     which holds the tgt tile after pass 2.
// ---------------------------------------------------------------------------
__global__ void __launch_bounds__(256, 1) k_tgt(
    const float* __restrict__ tgt, const float* __restrict__ g2,
    const float* __restrict__ b2, float* __restrict__ tgt_out) {
    extern __shared__ float smem[];
    float* Xs = smem;
    float* Ws = smem + D * D;
    int r0 = blockIdx.x * 128;
    int tc = threadIdx.x & 15, tr = threadIdx.x >> 4;
    float acc[8][8] = {};

    load_tile(Xs, g_agg, r0, NN);
    load_tile(Ws, g_wt + 3 * D * D, 0, D);
    __syncthreads();
    gemm128(Xs, Ws, acc, tr, tc);
    __syncthreads();

    load_tile(Xs, tgt, r0, NN);
    load_tile(Ws, g_wt + 4 * D * D, 0, D);
    __syncthreads();
    gemm128(Xs, Ws, acc, tr, tc);

    int c0 = tc * 8;
    float gg[8], bb[8];
    #pragma unroll
    for (int j = 0; j < 8; j++) { gg[j] = g2[c0 + j]; bb[j] = b2[c0 + j]; }

    #pragma unroll
    for (int i = 0; i < 8; i++) {
        int r = tr * 8 + i;
        int n = r0 + r;
        float s[8];
        float sum = 0.f, sq = 0.f;
        #pragma unroll
        for (int j = 0; j < 8; j++) {
            float sv = silu(acc[i][j]);
            s[j] = sv; sum += sv; sq += sv * sv;
        }
        #pragma unroll
        for (int o = 1; o < 16; o <<= 1) {
            sum += __shfl_xor_sync(0xffffffffu, sum, o);
            sq  += __shfl_xor_sync(0xffffffffu, sq,  o);
        }
        float mean = sum * (1.f / D);
        float var  = sq  * (1.f / D) - mean * mean;
        float rstd = rsqrtf(var + 1e-5f);
        if (n < NN) {
            float o8[8];
            #pragma unroll
            for (int j = 0; j < 8; j++)
                o8[j] = (s[j] - mean) * rstd * gg[j] + bb[j] + Xs[r * D + c0 + j];
            *(float4*)(tgt_out + (size_t)n * D + c0)     = make_float4(o8[0], o8[1], o8[2], o8[3]);
            *(float4*)(tgt_out + (size_t)n * D + c0 + 4) = make_float4(o8[4], o8[5], o8[6], o8[7]);
        }
    }
}

// ---------------------------------------------------------------------------
extern "C" void kernel_launch(void* const* d_in, const int* in_sizes, int n_in,
                              void* d_out, int out_size) {
    const float* src     = (const float*)d_in[0];
    const float* tgt     = (const float*)d_in[1];
    const float* edge    = (const float*)d_in[2];
    const int*   src_idx = (const int*)d_in[3];
    const int*   tgt_idx = (const int*)d_in[4];
    const float* W_s2e   = (const float*)d_in[5];
    const float* W_t2e   = (const float*)d_in[6];
    const float* W_e2e   = (const float*)d_in[7];
    const float* W_e2t   = (const float*)d_in[8];
    const float* W_t2t   = (const float*)d_in[9];
    const float* ln1_g   = (const float*)d_in[10];
    const float* ln1_b   = (const float*)d_in[11];
    const float* ln2_g   = (const float*)d_in[12];
    const float* ln2_b   = (const float*)d_in[13];

    float* edge_out = (float*)d_out;
    float* tgt_out  = edge_out + (size_t)NE * D;

    const size_t smem = 2 * D * D * sizeof(float);  // 128 KB
    cudaFuncSetAttribute(k_nodeproj, cudaFuncAttributeMaxDynamicSharedMemorySize, (int)smem);
    cudaFuncSetAttribute(k_edge,     cudaFuncAttributeMaxDynamicSharedMemorySize, (int)smem);
    cudaFuncSetAttribute(k_tgt,      cudaFuncAttributeMaxDynamicSharedMemorySize, (int)smem);

    k_zero<<<(NN * D / 4 + 255) / 256, 256>>>();
    k_transpose<<<5, 256>>>(W_s2e, W_t2e, W_e2e, W_e2t, W_t2t);
    dim3 gn((NN + 127) / 128, 2);
    k_nodeproj<<<gn, 256, smem>>>(src, tgt);
    k_edge<<<(NE + 127) / 128, 256, smem>>>(edge, src_idx, tgt_idx, ln1_g, ln1_b, edge_out);
    k_tgt<<<(NN + 127) / 128, 256, smem>>>(tgt, ln2_g, ln2_b, tgt_out);
}

// round 2
// speedup vs baseline: 1.0839x; 1.0839x over previous
#include <cuda_runtime.h>
#include <cstdint>

#define D 128
#define NN 50000
#define NE 500000
#define LDX 132            // padded X-tile row stride (floats): conflict-free, 16B-aligned
#define ROWS 64            // rows per block tile
#define TM 4               // rows per thread
// thread layout: 256 threads = 16 (tr) x 16 (tc); thread computes TM rows x 8 cols

// Scratch (allocation-free rule: __device__ globals)
__device__ float g_psrc[(size_t)NN * D];
__device__ float g_ptgt[(size_t)NN * D];
__device__ float g_agg [(size_t)NN * D];
__device__ float g_wt  [5 * D * D];      // transposed weights [k][j]

#define FMA2(d, a, b, c) \
    asm("fma.rn.f32x2 %0, %1, %2, %3;" : "=l"(d) : "l"(a), "l"(b), "l"(c))
#define PACK2(d, lo, hi) \
    asm("mov.b64 %0, {%1, %2};" : "=l"(d) : "r"(lo), "r"(hi))
#define UNPACK2(lo, hi, s) \
    asm("mov.b64 {%0, %1}, %2;" : "=r"(lo), "=r"(hi) : "l"(s))

// ---------------------------------------------------------------------------
__global__ void k_zero() {
    size_t i = ((size_t)blockIdx.x * blockDim.x + threadIdx.x) * 4;
    if (i < (size_t)NN * D) {
        *(float4*)(g_agg + i) = make_float4(0.f, 0.f, 0.f, 0.f);
    }
}

__global__ void k_transpose(const float* __restrict__ s2e, const float* __restrict__ t2e,
                            const float* __restrict__ e2e, const float* __restrict__ e2t,
                            const float* __restrict__ t2t) {
    const float* W[5] = {s2e, t2e, e2e, e2t, t2t};
    const float* src = W[blockIdx.x];
    float* dst = g_wt + blockIdx.x * D * D;
    for (int t = threadIdx.x; t < D * D; t += blockDim.x) {
        int k = t >> 7, j = t & 127;
        dst[t] = src[j * D + k];
    }
}

// ---------------------------------------------------------------------------
// Tile loaders: X tile = 64 rows x 128 cols, padded stride LDX.
// W tile = 128x128 dense copy.
// ---------------------------------------------------------------------------
__device__ __forceinline__ void load_xtile(float* dst, const float* __restrict__ src,
                                           int row0, int nrows) {
    int t = threadIdx.x;
    #pragma unroll
    for (int it = 0; it < 8; it++) {
        int i = t + it * 256;          // float4 index, 64*32 = 2048 total
        int r = i >> 5;
        int c = (i & 31) << 2;
        float4 v = make_float4(0.f, 0.f, 0.f, 0.f);
        if (row0 + r < nrows) v = *(const float4*)(src + (size_t)(row0 + r) * D + c);
        *(float4*)(dst + r * LDX + c) = v;
    }
}

__device__ __forceinline__ void load_wtile(float* dst, const float* __restrict__ src) {
    int t = threadIdx.x;
    #pragma unroll
    for (int it = 0; it < 16; it++) {
        int i = t + it * 256;          // 4096 float4
        ((float4*)dst)[i] = ((const float4*)src)[i];
    }
}

// ---------------------------------------------------------------------------
// 64x128 GEMM core with f32x2 packed FMAs.
// acc[i][p] : row (tr*4+i), column pair p of [c0 .. c0+7], c0 = tc*8
// ---------------------------------------------------------------------------
__device__ __forceinline__ void gemm64(const float* __restrict__ Xs,
                                       const float* __restrict__ Ws,
                                       uint64_t (&acc)[TM][4], int tr, int tc) {
    const float* xb = Xs + tr * TM * LDX;
    const float* wb = Ws + tc * 8;
    #pragma unroll 2
    for (int k0 = 0; k0 < D; k0 += 4) {
        float4 xv[TM];
        #pragma unroll
        for (int i = 0; i < TM; i++)
            xv[i] = *(const float4*)(xb + i * LDX + k0);
        #pragma unroll
        for (int kk = 0; kk < 4; kk++) {
            const float* wr = wb + (size_t)(k0 + kk) * D;
            ulonglong2 wA = *(const ulonglong2*)(wr);       // col pairs 0,1
            ulonglong2 wB = *(const ulonglong2*)(wr + 4);   // col pairs 2,3
            #pragma unroll
            for (int i = 0; i < TM; i++) {
                float xs = (kk == 0) ? xv[i].x : (kk == 1) ? xv[i].y
                         : (kk == 2) ? xv[i].z : xv[i].w;
                uint32_t xu = __float_as_uint(xs);
                uint64_t xp; PACK2(xp, xu, xu);
                FMA2(acc[i][0], xp, wA.x, acc[i][0]);
                FMA2(acc[i][1], xp, wA.y, acc[i][1]);
                FMA2(acc[i][2], xp, wB.x, acc[i][2]);
                FMA2(acc[i][3], xp, wB.y, acc[i][3]);
            }
        }
    }
}

__device__ __forceinline__ void unpack_row(const uint64_t* a, float* s) {
    #pragma unroll
    for (int p = 0; p < 4; p++) {
        uint32_t lo, hi;
        UNPACK2(lo, hi, a[p]);
        s[2 * p]     = __uint_as_float(lo);
        s[2 * p + 1] = __uint_as_float(hi);
    }
}

__device__ __forceinline__ float silu(float m) {
    return m * (1.f / (1.f + __expf(-m)));
}

// ---------------------------------------------------------------------------
// K1: node projections psrc/ptgt
// ---------------------------------------------------------------------------
__global__ void __launch_bounds__(256, 2) k_nodeproj(const float* __restrict__ src,
                                                     const float* __restrict__ tgt) {
    extern __shared__ float smem[];
    float* Xs = smem;
    float* Ws = smem + ROWS * LDX;
    int r0 = blockIdx.x * ROWS;
    const float* X;
    const float* Wt;
    float* O;
    if (blockIdx.y == 0) { X = src; Wt = g_wt;         O = g_psrc; }
    else                 { X = tgt; Wt = g_wt + D * D; O = g_ptgt; }
    load_xtile(Xs, X, r0, NN);
    load_wtile(Ws, Wt);
    __syncthreads();
    int tc = threadIdx.x & 15, tr = threadIdx.x >> 4;
    uint64_t acc[TM][4] = {};
    gemm64(Xs, Ws, acc, tr, tc);
    int c0 = tc * 8;
    #pragma unroll
    for (int i = 0; i < TM; i++) {
        int n = r0 + tr * TM + i;
        if (n < NN) {
            float s[8];
            unpack_row(acc[i], s);
            *(float4*)(O + (size_t)n * D + c0)     = make_float4(s[0], s[1], s[2], s[3]);
            *(float4*)(O + (size_t)n * D + c0 + 4) = make_float4(s[4], s[5], s[6], s[7]);
        }
    }
}

// ---------------------------------------------------------------------------
// K2: fused edge update + atomic aggregation (vector red.global)
// ---------------------------------------------------------------------------
__global__ void __launch_bounds__(256, 2) k_edge(
    const float* __restrict__ edge, const int* __restrict__ src_idx,
    const int* __restrict__ tgt_idx, const float* __restrict__ g1,
    const float* __restrict__ b1, float* __restrict__ edge_out) {
    extern __shared__ float smem[];
    float* Xs = smem;
    float* Ws = smem + ROWS * LDX;
    int e0 = blockIdx.x * ROWS;
    load_xtile(Xs, edge, e0, NE);
    load_wtile(Ws, g_wt + 2 * D * D);
    __syncthreads();
    int tc = threadIdx.x & 15, tr = threadIdx.x >> 4;
    uint64_t acc[TM][4] = {};
    gemm64(Xs, Ws, acc, tr, tc);

    int c0 = tc * 8;
    float gg[8], bb[8];
    #pragma unroll
    for (int j = 0; j < 8; j++) { gg[j] = g1[c0 + j]; bb[j] = b1[c0 + j]; }

    #pragma unroll
    for (int i = 0; i < TM; i++) {
        int r = tr * TM + i;
        int e = e0 + r;
        bool valid = e < NE;
        int si = valid ? src_idx[e] : 0;
        int ti = valid ? tgt_idx[e] : 0;
        const float* ps = g_psrc + (size_t)si * D + c0;
        const float* pt = g_ptgt + (size_t)ti * D + c0;
        float4 p0 = *(const float4*)ps;
        float4 p1 = *(const float4*)(ps + 4);
        float4 q0 = *(const float4*)pt;
        float4 q1 = *(const float4*)(pt + 4);
        float add[8] = {p0.x + q0.x, p0.y + q0.y, p0.z + q0.z, p0.w + q0.w,
                        p1.x + q1.x, p1.y + q1.y, p1.z + q1.z, p1.w + q1.w};
        float m[8];
        unpack_row(acc[i], m);
        float s[8];
        float sum = 0.f, sq = 0.f;
        #pragma unroll
        for (int j = 0; j < 8; j++) {
            float sv = silu(m[j] + add[j]);
            s[j] = sv; sum += sv; sq += sv * sv;
        }
        // half-warp reduction (a row's 16 threads are lanes [0..15] or [16..31])
        #pragma unroll
        for (int o = 1; o < 16; o <<= 1) {
            sum += __shfl_xor_sync(0xffffffffu, sum, o);
            sq  += __shfl_xor_sync(0xffffffffu, sq,  o);
        }
        float mean = sum * (1.f / D);
        float var  = sq  * (1.f / D) - mean * mean;
        float rstd = rsqrtf(var + 1e-5f);
        if (valid) {
            float o8[8];
            #pragma unroll
            for (int j = 0; j < 8; j++)
                o8[j] = (s[j] - mean) * rstd * gg[j] + bb[j] + Xs[r * LDX + c0 + j];
            *(float4*)(edge_out + (size_t)e * D + c0)     = make_float4(o8[0], o8[1], o8[2], o8[3]);
            *(float4*)(edge_out + (size_t)e * D + c0 + 4) = make_float4(o8[4], o8[5], o8[6], o8[7]);
            float* ap = g_agg + (size_t)ti * D + c0;
            asm volatile("red.global.add.v4.f32 [%0], {%1,%2,%3,%4};"
                         :: "l"(ap), "f"(o8[0]), "f"(o8[1]), "f"(o8[2]), "f"(o8[3]) : "memory");
            asm volatile("red.global.add.v4.f32 [%0], {%1,%2,%3,%4};"
                         :: "l"(ap + 4), "f"(o8[4]), "f"(o8[5]), "f"(o8[6]), "f"(o8[7]) : "memory");
        }
    }
}

// ---------------------------------------------------------------------------
// K3: target update (two accumulated GEMM passes + fused epilogue)
// ---------------------------------------------------------------------------
__global__ void __launch_bounds__(256, 2) k_tgt(
    const float* __restrict__ tgt, const float* __restrict__ g2,
    const float* __restrict__ b2, float* __restrict__ tgt_out) {
    extern __shared__ float smem[];
    float* Xs = smem;
    float* Ws = smem + ROWS * LDX;
    int r0 = blockIdx.x * ROWS;
    int tc = threadIdx.x & 15, tr = threadIdx.x >> 4;
    uint64_t acc[TM][4] = {};

    load_xtile(Xs, g_agg, r0, NN);
    load_wtile(Ws, g_wt + 3 * D * D);
    __syncthreads();
    gemm64(Xs, Ws, acc, tr, tc);
    __syncthreads();

    load_xtile(Xs, tgt, r0, NN);
    load_wtile(Ws, g_wt + 4 * D * D);
    __syncthreads();
    gemm64(Xs, Ws, acc, tr, tc);

    int c0 = tc * 8;
    float gg[8], bb[8];
    #pragma unroll
    for (int j = 0; j < 8; j++) { gg[j] = g2[c0 + j]; bb[j] = b2[c0 + j]; }

    #pragma unroll
    for (int i = 0; i < TM; i++) {
        int r = tr * TM + i;
        int n = r0 + r;
        float m[8];
        unpack_row(acc[i], m);
        float s[8];
        float sum = 0.f, sq = 0.f;
        #pragma unroll
        for (int j = 0; j < 8; j++) {
            float sv = silu(m[j]);
            s[j] = sv; sum += sv; sq += sv * sv;
        }
        #pragma unroll
        for (int o = 1; o < 16; o <<= 1) {
            sum += __shfl_xor_sync(0xffffffffu, sum, o);
            sq  += __shfl_xor_sync(0xffffffffu, sq,  o);
        }
        float mean = sum * (1.f / D);
        float var  = sq  * (1.f / D) - mean * mean;
        float rstd = rsqrtf(var + 1e-5f);
        if (n < NN) {
            float o8[8];
            #pragma unroll
            for (int j = 0; j < 8; j++)
                o8[j] = (s[j] - mean) * rstd * gg[j] + bb[j] + Xs[r * LDX + c0 + j];
            *(float4*)(tgt_out + (size_t)n * D + c0)     = make_float4(o8[0], o8[1], o8[2], o8[3]);
            *(float4*)(tgt_out + (size_t)n * D + c0 + 4) = make_float4(o8[4], o8[5], o8[6], o8[7]);
        }
    }
}

// ---------------------------------------------------------------------------
extern "C" void kernel_launch(void* const* d_in, const int* in_sizes, int n_in,
                              void* d_out, int out_size) {
    const float* src     = (const float*)d_in[0];
    const float* tgt     = (const float*)d_in[1];
    const float* edge    = (const float*)d_in[2];
    const int*   src_idx = (const int*)d_in[3];
    const int*   tgt_idx = (const int*)d_in[4];
    const float* W_s2e   = (const float*)d_in[5];
    const float* W_t2e   = (const float*)d_in[6];
    const float* W_e2e   = (const float*)d_in[7];
    const float* W_e2t   = (const float*)d_in[8];
    const float* W_t2t   = (const float*)d_in[9];
    const float* ln1_g   = (const float*)d_in[10];
    const float* ln1_b   = (const float*)d_in[11];
    const float* ln2_g   = (const float*)d_in[12];
    const float* ln2_b   = (const float*)d_in[13];

    float* edge_out = (float*)d_out;
    float* tgt_out  = edge_out + (size_t)NE * D;

    const size_t smem = (ROWS * LDX + D * D) * sizeof(float);  // ~97KB
    cudaFuncSetAttribute(k_nodeproj, cudaFuncAttributeMaxDynamicSharedMemorySize, (int)smem);
    cudaFuncSetAttribute(k_edge,     cudaFuncAttributeMaxDynamicSharedMemorySize, (int)smem);
    cudaFuncSetAttribute(k_tgt,      cudaFuncAttributeMaxDynamicSharedMemorySize, (int)smem);

    k_zero<<<(NN * D / 4 + 255) / 256, 256>>>();
    k_transpose<<<5, 256>>>(W_s2e, W_t2e, W_e2e, W_e2t, W_t2t);
    dim3 gn((NN + ROWS - 1) / ROWS, 2);
    k_nodeproj<<<gn, 256, smem>>>(src, tgt);
    k_edge<<<(NE + ROWS - 1) / ROWS, 256, smem>>>(edge, src_idx, tgt_idx, ln1_g, ln1_b, edge_out);
    k_tgt<<<(NN + ROWS - 1) / ROWS, 256, smem>>>(tgt, ln2_g, ln2_b, tgt_out);
}